// round 11
// baseline (speedup 1.0000x reference)
#include <cuda_runtime.h>
#include <cuda_bf16.h>
#include <math.h>

// Problem constants
#define B_   8
#define T_   8192
#define C_   128
#define H_   8
#define T0_  16
#define NP_  512           // T/T0
#define S_   65            // 4 patches * 16 + 1 sink
#define EPS_ 1.1920929e-07f

// Scratch (device globals; no allocation allowed)
__device__ float g_logits[B_ * NP_];             // 4096
__device__ int   g_topk[B_ * 4];                 // sorted patch indices per batch
__device__ float g_gn[B_ * H_ * 64 * 128];       // sigmoid(g) scratch (per-block reuse)
__device__ float g_y[B_ * 64 * 1024];            // gated attention output
__device__ float g_part[4 * B_ * 64 * 128];      // split-K partials of final GEMM

// Packed fp32 pair FMA: d = a*b + d (both lanes)
__device__ __forceinline__ void ffma2(float2& d, float2 a, float2 b) {
    asm("fma.rn.f32x2 %0, %1, %2, %0;"
        : "+l"(reinterpret_cast<unsigned long long&>(d))
        : "l"(reinterpret_cast<unsigned long long&>(a)),
          "l"(reinterpret_cast<unsigned long long&>(b)));
}

__device__ __forceinline__ float tf32f(float f) {
    float r;
    asm("cvt.rna.tf32.f32 %0, %1;" : "=f"(r) : "f"(f));
    return r;
}

__device__ __forceinline__ void mma_tf32(float& c0, float& c1, float& c2, float& c3,
                                         unsigned a0, unsigned a1, unsigned a2, unsigned a3,
                                         unsigned b0, unsigned b1) {
    asm volatile("mma.sync.aligned.m16n8k8.row.col.f32.tf32.tf32.f32 "
        "{%0,%1,%2,%3}, {%4,%5,%6,%7}, {%8,%9}, {%0,%1,%2,%3};"
        : "+f"(c0), "+f"(c1), "+f"(c2), "+f"(c3)
        : "r"(a0), "r"(a1), "r"(a2), "r"(a3), "r"(b0), "r"(b1));
}

// ---------------------------------------------------------------------------
// Kernel 1: patch score logits.
// ---------------------------------------------------------------------------
__global__ void patch_score_kernel(const float* __restrict__ x,
                                   const float* __restrict__ pw) {
    int blk = blockIdx.x;                  // b*512 + p
    const float4* v = reinterpret_cast<const float4*>(x + (size_t)blk * 2048);
    const float4* w = reinterpret_cast<const float4*>(pw);
    float ssq = 0.f, dot = 0.f;
    for (int i = threadIdx.x; i < 512; i += 256) {
        float4 a = v[i];
        float4 b = w[i];
        ssq += a.x * a.x + a.y * a.y + a.z * a.z + a.w * a.w;
        dot += a.x * b.x + a.y * b.y + a.z * b.z + a.w * b.w;
    }
    for (int off = 16; off; off >>= 1) {
        ssq += __shfl_xor_sync(0xffffffffu, ssq, off);
        dot += __shfl_xor_sync(0xffffffffu, dot, off);
    }
    __shared__ float red[16];
    int wid = threadIdx.x >> 5, lane = threadIdx.x & 31;
    if (lane == 0) { red[wid] = ssq; red[8 + wid] = dot; }
    __syncthreads();
    if (threadIdx.x == 0) {
        float S = 0.f, D = 0.f;
        for (int wv = 0; wv < 8; wv++) { S += red[wv]; D += red[8 + wv]; }
        g_logits[blk] = D * rsqrtf(S * (1.0f / 2048.0f) + EPS_);
    }
}

// ---------------------------------------------------------------------------
// Kernel 2: top-4 per batch, sorted ascending. One warp per batch.
// ---------------------------------------------------------------------------
__global__ void topk_kernel() {
    int b = blockIdx.x;
    int lane = threadIdx.x;   // 32 threads
    float vals[16];
    for (int i = 0; i < 16; i++) vals[i] = g_logits[b * NP_ + lane * 16 + i];
    int chosen[4];
    for (int r = 0; r < 4; r++) {
        float best = -3.4e38f;
        int bi = 0x7fffffff;
        for (int i = 0; i < 16; i++) {
            int idx = lane * 16 + i;
            bool used = false;
            for (int j = 0; j < r; j++) if (chosen[j] == idx) used = true;
            if (!used && vals[i] > best) { best = vals[i]; bi = idx; }
        }
        for (int off = 16; off; off >>= 1) {
            float ov = __shfl_down_sync(0xffffffffu, best, off);
            int   oi = __shfl_down_sync(0xffffffffu, bi, off);
            if (ov > best || (ov == best && oi < bi)) { best = ov; bi = oi; }
        }
        bi = __shfl_sync(0xffffffffu, bi, 0);
        chosen[r] = bi;
    }
    if (lane == 0) {
        for (int i = 0; i < 3; i++)
            for (int j = i + 1; j < 4; j++)
                if (chosen[j] < chosen[i]) { int t = chosen[i]; chosen[i] = chosen[j]; chosen[j] = t; }
        for (int i = 0; i < 4; i++) g_topk[b * 4 + i] = chosen[i];
    }
}

// ---------------------------------------------------------------------------
// Kernel 3 (FUSED): per-(b,h) qkvg tf32-MMA + rope/rmsnorm/sigmoid epilogue
// + full attention + gating. Grid 64, 512 threads, ~222 KB smem.
// Gate values go to global scratch g_gn (smem has no room; ~32KB/block L2
// round-trip, ordered by the __syncthreads between epilogue and AV phase).
// ---------------------------------------------------------------------------
__global__ void __launch_bounds__(512, 1)
fused_kernel(const float* __restrict__ x,
             const float* __restrict__ W,
             const float* __restrict__ cosp,
             const float* __restrict__ sinp,
             const float* __restrict__ sink,
             const float* __restrict__ tao) {
    extern __shared__ float sm[];
    float* xs   = sm;                    // 8448  (64*132)
    float* wb   = sm + 8448;             // 16896 (128*132) W chunk / frag staging
    float* qs   = sm + 25344;            // 8580  (65*132)
    float* ks_  = qs + 8580;             // 8580
    float* vs   = ks_ + 8580;            // 8580
    float* att  = vs + 8580;             // 4420  (65*68)

    int bh = blockIdx.x;
    int b = bh >> 3, h = bh & 7;
    int tid = threadIdx.x;
    int warp = tid >> 5;                 // 0..15
    int lane = tid & 31;
    float t0v = tao[0], t1v = tao[1];
    float* gate = g_gn + (size_t)bh * 64 * 128;

    // zero att (upper triangle must stay 0 for guard-free AV)
    for (int i = tid; i < 65 * 68; i += 512) att[i] = 0.f;

    // sink row 0 (rope at s=0 is identity)
    if (warp == 15) {
        float4 a = *reinterpret_cast<const float4*>(sink + h * 128 + lane * 4);
        float ss = a.x * a.x + a.y * a.y + a.z * a.z + a.w * a.w;
        for (int off = 16; off; off >>= 1) ss += __shfl_xor_sync(0xffffffffu, ss, off);
        float rq = rsqrtf(ss * (1.0f / 128.0f) + EPS_) * t0v;
        float rk = rsqrtf(ss * (1.0f / 128.0f) + EPS_) * t1v;
        *reinterpret_cast<float4*>(qs + lane * 4)  = make_float4(a.x * rq, a.y * rq, a.z * rq, a.w * rq);
        *reinterpret_cast<float4*>(ks_ + lane * 4) = make_float4(a.x * rk, a.y * rk, a.z * rk, a.w * rk);
        *reinterpret_cast<float4*>(vs + lane * 4)  = a;
    }

    // gather x tokens (tf32-converted)
    for (int i = tid; i < 2048; i += 512) {
        int m  = i >> 5;
        int c4 = i & 31;
        int tok = g_topk[b * 4 + (m >> 4)] * T0_ + (m & 15);
        float4 v = reinterpret_cast<const float4*>(x + ((size_t)b * T_ + tok) * C_)[c4];
        v.x = tf32f(v.x); v.y = tf32f(v.y); v.z = tf32f(v.z); v.w = tf32f(v.w);
        *reinterpret_cast<float4*>(xs + m * 132 + c4 * 4) = v;
    }
    __syncthreads();

    int g = lane >> 2;            // 0..7
    int t = lane & 3;             // 0..3
    int wn = warp * 8;            // n-subtile base
    const unsigned* xsu = reinterpret_cast<const unsigned*>(xs);
    const unsigned* wbu = reinterpret_cast<const unsigned*>(wb);
    int comp = warp & 3;          // 0=q 1=k 2=v 3=g
    int j    = warp >> 2;         // patch

    for (int c2 = 0; c2 < 4; c2++) {
        // load W chunk: rows c2*1024 + h*128 + (0..127)
        const float* Wrow = W + (size_t)(c2 * 1024 + h * 128) * C_;
        for (int i = tid; i < 4096; i += 512) {
            int n  = i >> 5;
            int k4 = i & 31;
            float4 v = reinterpret_cast<const float4*>(Wrow + (size_t)n * C_)[k4];
            v.x = tf32f(v.x); v.y = tf32f(v.y); v.z = tf32f(v.z); v.w = tf32f(v.w);
            *reinterpret_cast<float4*>(wb + n * 132 + k4 * 4) = v;
        }
        __syncthreads();

        float c[4][4];
#pragma unroll
        for (int mt = 0; mt < 4; mt++)
#pragma unroll
            for (int q = 0; q < 4; q++) c[mt][q] = 0.f;

#pragma unroll 4
        for (int ksi = 0; ksi < 16; ksi++) {
            int k0 = ksi * 8;
            unsigned b0 = wbu[(wn + g) * 132 + k0 + t];
            unsigned b1 = wbu[(wn + g) * 132 + k0 + t + 4];
#pragma unroll
            for (int mt = 0; mt < 4; mt++) {
                unsigned a0 = xsu[(mt * 16 + g) * 132 + k0 + t];
                unsigned a1 = xsu[(mt * 16 + g + 8) * 132 + k0 + t];
                unsigned a2 = xsu[(mt * 16 + g) * 132 + k0 + t + 4];
                unsigned a3 = xsu[(mt * 16 + g + 8) * 132 + k0 + t + 4];
                mma_tf32(c[mt][0], c[mt][1], c[mt][2], c[mt][3], a0, a1, a2, a3, b0, b1);
            }
        }
        __syncthreads();          // W reads done; reuse wb rows 0..63 as staging

#pragma unroll
        for (int mt = 0; mt < 4; mt++) {
            *reinterpret_cast<float2*>(wb + (mt * 16 + g) * 132 + wn + 2 * t) =
                make_float2(c[mt][0], c[mt][1]);
            *reinterpret_cast<float2*>(wb + (mt * 16 + g + 8) * 132 + wn + 2 * t) =
                make_float2(c[mt][2], c[mt][3]);
        }
        __syncthreads();

        // epilogue: warp = 4 rows of one comp, lane = 4 channels
#pragma unroll
        for (int mm = 0; mm < 4; mm++) {
            int m = warp * 4 + mm;
            float4 val = *reinterpret_cast<const float4*>(wb + m * 132 + lane * 4);
            int sp = j * 16 + 4 * mm + c2;   // seq position (0..63)
            int s  = sp + 1;                 // incl. sink offset
            if (comp == 2) {
                *reinterpret_cast<float4*>(vs + s * 132 + lane * 4) = val;
            } else if (comp == 3) {
                float4 o;
                o.x = 1.f / (1.f + __expf(-val.x));
                o.y = 1.f / (1.f + __expf(-val.y));
                o.z = 1.f / (1.f + __expf(-val.z));
                o.w = 1.f / (1.f + __expf(-val.w));
                *reinterpret_cast<float4*>(gate + sp * 128 + lane * 4) = o;
            } else {
                // rope: partner lane (lane^16) holds the paired half
                float4 p;
                p.x = __shfl_xor_sync(0xffffffffu, val.x, 16);
                p.y = __shfl_xor_sync(0xffffffffu, val.y, 16);
                p.z = __shfl_xor_sync(0xffffffffu, val.z, 16);
                p.w = __shfl_xor_sync(0xffffffffu, val.w, 16);
                float4 cs = *reinterpret_cast<const float4*>(cosp + s * 64 + (lane & 15) * 4);
                float4 sn = *reinterpret_cast<const float4*>(sinp + s * 64 + (lane & 15) * 4);
                float sgn = (lane < 16) ? 1.f : -1.f;
                float4 o;
                o.x = val.x * cs.x + sgn * p.x * sn.x;
                o.y = val.y * cs.y + sgn * p.y * sn.y;
                o.z = val.z * cs.z + sgn * p.z * sn.z;
                o.w = val.w * cs.w + sgn * p.w * sn.w;
                float ss = o.x * o.x + o.y * o.y + o.z * o.z + o.w * o.w;
                for (int off = 16; off; off >>= 1) ss += __shfl_xor_sync(0xffffffffu, ss, off);
                float rn = rsqrtf(ss * (1.0f / 128.0f) + EPS_) * (comp == 0 ? t0v : t1v);
                o.x *= rn; o.y *= rn; o.z *= rn; o.w *= rn;
                float* dst = (comp == 0 ? qs : ks_) + s * 132 + lane * 4;
                *reinterpret_cast<float4*>(dst) = o;
            }
        }
        __syncthreads();
    }

    // ---- Score phase: task = (group of 4 rows, 32-key chunk), rows s=i ----
    const float scale = 0.08838834764831845f;  // 1/sqrt(128)
    for (int task = warp; task < 51; task += 16) {
        int g2 = task / 3;
        int c  = task - g2 * 3;
        int i0 = g2 * 4;
        int smax = min(i0 + 3, 64);
        int t0 = c * 32;
        if (t0 > smax) continue;
        int tt = t0 + lane;
        int te = (tt < 64) ? tt : 64;
        int ie0 = min(i0 + 0, 64);
        int ie1 = min(i0 + 1, 64);
        int ie2 = min(i0 + 2, 64);
        int ie3 = min(i0 + 3, 64);

        const float4* kr = reinterpret_cast<const float4*>(ks_ + te * 132);
        const float4* q0 = reinterpret_cast<const float4*>(qs + ie0 * 132);
        const float4* q1 = reinterpret_cast<const float4*>(qs + ie1 * 132);
        const float4* q2 = reinterpret_cast<const float4*>(qs + ie2 * 132);
        const float4* q3 = reinterpret_cast<const float4*>(qs + ie3 * 132);

        float2 p00 = {0,0}, p01 = {0,0}, p10 = {0,0}, p11 = {0,0};
        float2 p20 = {0,0}, p21 = {0,0}, p30 = {0,0}, p31 = {0,0};
#pragma unroll 8
        for (int c4 = 0; c4 < 32; c4++) {
            float4 kv = kr[c4];
            float2 k0 = make_float2(kv.x, kv.y);
            float2 k1 = make_float2(kv.z, kv.w);
            float4 v0 = q0[c4];
            ffma2(p00, make_float2(v0.x, v0.y), k0);
            ffma2(p01, make_float2(v0.z, v0.w), k1);
            float4 v1 = q1[c4];
            ffma2(p10, make_float2(v1.x, v1.y), k0);
            ffma2(p11, make_float2(v1.z, v1.w), k1);
            float4 v2 = q2[c4];
            ffma2(p20, make_float2(v2.x, v2.y), k0);
            ffma2(p21, make_float2(v2.z, v2.w), k1);
            float4 v3 = q3[c4];
            ffma2(p30, make_float2(v3.x, v3.y), k0);
            ffma2(p31, make_float2(v3.z, v3.w), k1);
        }
        float r0 = (p00.x + p00.y) + (p01.x + p01.y);
        float r1 = (p10.x + p10.y) + (p11.x + p11.y);
        float r2 = (p20.x + p20.y) + (p21.x + p21.y);
        float r3 = (p30.x + p30.y) + (p31.x + p31.y);
        if (i0 + 0 <= 64 && tt <= i0 + 0) att[(i0 + 0) * 68 + tt] = r0 * scale;
        if (i0 + 1 <= 64 && tt <= i0 + 1) att[(i0 + 1) * 68 + tt] = r1 * scale;
        if (i0 + 2 <= 64 && tt <= i0 + 2) att[(i0 + 2) * 68 + tt] = r2 * scale;
        if (i0 + 3 <= 64 && tt <= i0 + 3) att[(i0 + 3) * 68 + tt] = r3 * scale;
    }
    __syncthreads();

    // ---- Softmax: one warp per row ----------------------------------------
    for (int i = warp; i < 65; i += 16) {
        int s = i;
        float v0 = (lane      <= s) ? att[i * 68 + lane]      : -3.4e38f;
        float v1 = (lane + 32 <= s) ? att[i * 68 + lane + 32] : -3.4e38f;
        float v2 = (lane + 64 <= s) ? att[i * 68 + lane + 64] : -3.4e38f;
        float m = fmaxf(fmaxf(v0, v1), v2);
        for (int off = 16; off; off >>= 1) m = fmaxf(m, __shfl_xor_sync(0xffffffffu, m, off));
        float e0 = (lane      <= s) ? __expf(v0 - m) : 0.f;
        float e1 = (lane + 32 <= s) ? __expf(v1 - m) : 0.f;
        float e2 = (lane + 64 <= s) ? __expf(v2 - m) : 0.f;
        float sum = e0 + e1 + e2;
        for (int off = 16; off; off >>= 1) sum += __shfl_xor_sync(0xffffffffu, sum, off);
        float inv = 1.f / sum;
        if (lane      <= s) att[i * 68 + lane]      = e0 * inv;
        if (lane + 32 <= s) att[i * 68 + lane + 32] = e1 * inv;
        if (lane + 64 <= s) att[i * 68 + lane + 64] = e2 * inv;
    }
    __syncthreads();

    // ---- AV phase: warp owns rows i = warp + 16*jj ------------------------
    {
        int nj = (80 - warp) >> 4;              // 5 for warp 0, else 4
        float2 accp[5][2];
#pragma unroll
        for (int jj = 0; jj < 5; jj++) {
            accp[jj][0] = make_float2(0.f, 0.f);
            accp[jj][1] = make_float2(0.f, 0.f);
        }
        int tmax = warp + 16 * (nj - 1);        // = s of last owned row
        for (int tt = 0; tt <= tmax; tt++) {
            float4 vv = *reinterpret_cast<const float4*>(vs + tt * 132 + lane * 4);
            float2 vp0 = make_float2(vv.x, vv.y);
            float2 vp1 = make_float2(vv.z, vv.w);
#pragma unroll
            for (int jj = 0; jj < 5; jj++) {
                if (jj < nj) {
                    float a = att[(warp + 16 * jj) * 68 + tt];   // 0 for tt > s
                    float2 ap = make_float2(a, a);
                    ffma2(accp[jj][0], ap, vp0);
                    ffma2(accp[jj][1], ap, vp1);
                }
            }
        }
#pragma unroll
        for (int jj = 0; jj < 5; jj++) {
            if (jj < nj) {
                int s = warp + 16 * jj;
                if (s == 0) continue;            // sink row dropped
                int sp = s - 1;
                float4 gv = *reinterpret_cast<const float4*>(gate + sp * 128 + lane * 4);
                float4 o;
                o.x = accp[jj][0].x * gv.x;
                o.y = accp[jj][0].y * gv.y;
                o.z = accp[jj][1].x * gv.z;
                o.w = accp[jj][1].y * gv.w;
                *reinterpret_cast<float4*>(
                    g_y + (size_t)(b * 64 + sp) * 1024 + h * C_ + lane * 4) = o;
            }
        }
    }
}

// ---------------------------------------------------------------------------
// Kernel 5: output GEMM (split-K), f32x2 pairs over n.
// ---------------------------------------------------------------------------
__global__ void outgemm_kernel(const float* __restrict__ Wout) {
    __shared__ float ys[64 * 128];
    __shared__ float ws[128 * 32];   // [k][n]
    int n0  = blockIdx.x * 32;
    int ksb = blockIdx.y;
    int b   = blockIdx.z;
    int tid = threadIdx.x;           // 256

    float2 acc2[2][2];
#pragma unroll
    for (int mm = 0; mm < 2; mm++) {
        acc2[mm][0] = make_float2(0.f, 0.f);
        acc2[mm][1] = make_float2(0.f, 0.f);
    }

    for (int kc = 0; kc < 2; kc++) {
        int k0 = ksb * 256 + kc * 128;
        __syncthreads();
        for (int i = tid; i < 2048; i += 256) {
            int m = i >> 5, k4 = i & 31;
            reinterpret_cast<float4*>(ys)[i] =
                *reinterpret_cast<const float4*>(g_y + (size_t)(b * 64 + m) * 1024 + k0 + k4 * 4);
        }
        for (int i = tid; i < 1024; i += 256) {
            int n = i >> 5, k4 = i & 31;
            float4 w4 = *reinterpret_cast<const float4*>(Wout + (size_t)(n0 + n) * 1024 + k0 + k4 * 4);
            int k = k4 * 4;
            ws[(k + 0) * 32 + n] = w4.x;
            ws[(k + 1) * 32 + n] = w4.y;
            ws[(k + 2) * 32 + n] = w4.z;
            ws[(k + 3) * 32 + n] = w4.w;
        }
        __syncthreads();

        int ty = tid >> 3;   // rows {ty, ty+32}
        int tx = tid & 7;    // cols tx*4..+3
#pragma unroll 4
        for (int k = 0; k < 128; k++) {
            float4 b4 = reinterpret_cast<const float4*>(ws + k * 32)[tx];
            float2 bp0 = make_float2(b4.x, b4.y);
            float2 bp1 = make_float2(b4.z, b4.w);
            float a0 = ys[ty * 128 + k];
            float a1 = ys[(ty + 32) * 128 + k];
            float2 ap0 = make_float2(a0, a0);
            float2 ap1 = make_float2(a1, a1);
            ffma2(acc2[0][0], ap0, bp0);
            ffma2(acc2[0][1], ap0, bp1);
            ffma2(acc2[1][0], ap1, bp0);
            ffma2(acc2[1][1], ap1, bp1);
        }
    }

    int ty = tid >> 3, tx = tid & 7;
#pragma unroll
    for (int mm = 0; mm < 2; mm++) {
        int m = ty + mm * 32;
        float4 o = make_float4(acc2[mm][0].x, acc2[mm][0].y, acc2[mm][1].x, acc2[mm][1].y);
        reinterpret_cast<float4*>(g_part + (size_t)ksb * 65536
                                  + (size_t)(b * 64 + m) * 128 + n0)[tx] = o;
    }
}

__global__ void reduce_kernel(float* __restrict__ out) {
    int i = blockIdx.x * 256 + threadIdx.x;
    out[i] = ((g_part[i] + g_part[65536 + i]) + g_part[131072 + i]) + g_part[196608 + i];
}

// ---------------------------------------------------------------------------
extern "C" void kernel_launch(void* const* d_in, const int* in_sizes, int n_in,
                              void* d_out, int out_size) {
    const float* x      = (const float*)d_in[0];
    const float* cosp   = (const float*)d_in[1];
    const float* sinp   = (const float*)d_in[2];
    const float* sink   = (const float*)d_in[3];
    const float* W_qkvg = (const float*)d_in[4];
    const float* patchw = (const float*)d_in[5];
    const float* W_out  = (const float*)d_in[6];
    const float* tao    = (const float*)d_in[7];
    float* out = (float*)d_out;

    const int smemF = (8448 + 16896 + 3 * 8580 + 4420) * 4;   // 222016 B
    cudaFuncSetAttribute(fused_kernel, cudaFuncAttributeMaxDynamicSharedMemorySize, smemF);

    patch_score_kernel<<<B_ * NP_, 256>>>(x, patchw);
    topk_kernel<<<B_, 32>>>();
    fused_kernel<<<B_ * H_, 512, smemF>>>(x, W_qkvg, cosp, sinp, sink, tao);
    outgemm_kernel<<<dim3(4, 4, B_), 256>>>(W_out);
    reduce_kernel<<<B_ * 64 * 128 / 256, 256>>>(out);
}

// round 15
// speedup vs baseline: 1.9038x; 1.9038x over previous
#include <cuda_runtime.h>
#include <cuda_bf16.h>
#include <math.h>

// Problem constants
#define B_   8
#define T_   8192
#define C_   128
#define H_   8
#define T0_  16
#define NP_  512           // T/T0
#define S_   65            // 4 patches * 16 + 1 sink
#define EPS_ 1.1920929e-07f

// Scratch (device globals; no allocation allowed)
__device__ float g_logits[B_ * NP_];             // 4096
__device__ int   g_topk[B_ * 4];                 // sorted patch indices per batch
__device__ float g_qn[B_ * H_ * 65 * 128];       // prenormed q (rope+rmsnorm+tao0), row 0 = sink
__device__ float g_kn[B_ * H_ * 65 * 128];       // prenormed k
__device__ float g_vn[B_ * H_ * 65 * 128];       // raw v
__device__ float g_gn[B_ * H_ * 64 * 128];       // sigmoid(g)
__device__ float g_y[B_ * 64 * 1024];            // gated attention output
__device__ float g_part[8 * B_ * 64 * 128];      // split-K partials of final GEMM

// Packed fp32 pair FMA: d = a*b + d (both lanes)
__device__ __forceinline__ void ffma2(float2& d, float2 a, float2 b) {
    asm("fma.rn.f32x2 %0, %1, %2, %0;"
        : "+l"(reinterpret_cast<unsigned long long&>(d))
        : "l"(reinterpret_cast<unsigned long long&>(a)),
          "l"(reinterpret_cast<unsigned long long&>(b)));
}

__device__ __forceinline__ float tf32f(float f) {
    float r;
    asm("cvt.rna.tf32.f32 %0, %1;" : "=f"(r) : "f"(f));
    return r;
}

__device__ __forceinline__ void mma_tf32(float& c0, float& c1, float& c2, float& c3,
                                         unsigned a0, unsigned a1, unsigned a2, unsigned a3,
                                         unsigned b0, unsigned b1) {
    asm volatile("mma.sync.aligned.m16n8k8.row.col.f32.tf32.tf32.f32 "
        "{%0,%1,%2,%3}, {%4,%5,%6,%7}, {%8,%9}, {%0,%1,%2,%3};"
        : "+f"(c0), "+f"(c1), "+f"(c2), "+f"(c3)
        : "r"(a0), "r"(a1), "r"(a2), "r"(a3), "r"(b0), "r"(b1));
}

// ---------------------------------------------------------------------------
// Kernel 1: patch score logits.
// ---------------------------------------------------------------------------
__global__ void patch_score_kernel(const float* __restrict__ x,
                                   const float* __restrict__ pw) {
    int blk = blockIdx.x;                  // b*512 + p
    const float4* v = reinterpret_cast<const float4*>(x + (size_t)blk * 2048);
    const float4* w = reinterpret_cast<const float4*>(pw);
    float ssq = 0.f, dot = 0.f;
    for (int i = threadIdx.x; i < 512; i += 256) {
        float4 a = v[i];
        float4 b = w[i];
        ssq += a.x * a.x + a.y * a.y + a.z * a.z + a.w * a.w;
        dot += a.x * b.x + a.y * b.y + a.z * b.z + a.w * b.w;
    }
    for (int off = 16; off; off >>= 1) {
        ssq += __shfl_xor_sync(0xffffffffu, ssq, off);
        dot += __shfl_xor_sync(0xffffffffu, dot, off);
    }
    __shared__ float red[16];
    int wid = threadIdx.x >> 5, lane = threadIdx.x & 31;
    if (lane == 0) { red[wid] = ssq; red[8 + wid] = dot; }
    __syncthreads();
    if (threadIdx.x == 0) {
        float S = 0.f, D = 0.f;
        for (int wv = 0; wv < 8; wv++) { S += red[wv]; D += red[8 + wv]; }
        g_logits[blk] = D * rsqrtf(S * (1.0f / 2048.0f) + EPS_);
    }
}

// ---------------------------------------------------------------------------
// Kernel 2: top-4 per batch, sorted ascending. One warp per batch.
// ---------------------------------------------------------------------------
__global__ void topk_kernel() {
    int b = blockIdx.x;
    int lane = threadIdx.x;   // 32 threads
    float vals[16];
    for (int i = 0; i < 16; i++) vals[i] = g_logits[b * NP_ + lane * 16 + i];
    int chosen[4];
    for (int r = 0; r < 4; r++) {
        float best = -3.4e38f;
        int bi = 0x7fffffff;
        for (int i = 0; i < 16; i++) {
            int idx = lane * 16 + i;
            bool used = false;
            for (int j = 0; j < r; j++) if (chosen[j] == idx) used = true;
            if (!used && vals[i] > best) { best = vals[i]; bi = idx; }
        }
        for (int off = 16; off; off >>= 1) {
            float ov = __shfl_down_sync(0xffffffffu, best, off);
            int   oi = __shfl_down_sync(0xffffffffu, bi, off);
            if (ov > best || (ov == best && oi < bi)) { best = ov; bi = oi; }
        }
        bi = __shfl_sync(0xffffffffu, bi, 0);
        chosen[r] = bi;
    }
    if (lane == 0) {
        for (int i = 0; i < 3; i++)
            for (int j = i + 1; j < 4; j++)
                if (chosen[j] < chosen[i]) { int t = chosen[i]; chosen[i] = chosen[j]; chosen[j] = t; }
        for (int i = 0; i < 4; i++) g_topk[b * 4 + i] = chosen[i];
    }
}

// ---------------------------------------------------------------------------
// Kernel 2b: sink row prep. rope at s=0 is identity (cos=1, sin=0).
// ---------------------------------------------------------------------------
__global__ void sink_prep_kernel(const float* __restrict__ sink,
                                 const float* __restrict__ tao) {
    int warp = threadIdx.x >> 5;   // h (0..7)
    int lane = threadIdx.x & 31;
    float t0v = tao[0], t1v = tao[1];
    float4 a = *reinterpret_cast<const float4*>(sink + warp * 128 + lane * 4);
    float ss = a.x * a.x + a.y * a.y + a.z * a.z + a.w * a.w;
    for (int off = 16; off; off >>= 1) ss += __shfl_xor_sync(0xffffffffu, ss, off);
    float rq = rsqrtf(ss * (1.0f / 128.0f) + EPS_) * t0v;
    float rk = rsqrtf(ss * (1.0f / 128.0f) + EPS_) * t1v;
    float4 q = make_float4(a.x * rq, a.y * rq, a.z * rq, a.w * rq);
    float4 k = make_float4(a.x * rk, a.y * rk, a.z * rk, a.w * rk);
    for (int b = 0; b < 8; b++) {
        size_t base = ((size_t)(b * 8 + warp) * 65) * 128 + lane * 4;
        *reinterpret_cast<float4*>(g_qn + base) = q;
        *reinterpret_cast<float4*>(g_kn + base) = k;
        *reinterpret_cast<float4*>(g_vn + base) = a;
    }
}

// ---------------------------------------------------------------------------
// Kernel 3: qkvg projection via tf32 mma.sync + fused rope/rmsnorm/sigmoid
// epilogue. Block n-tile = one (component c2, head h). 512 threads, 16 warps.
// ---------------------------------------------------------------------------
__global__ void __launch_bounds__(512, 2)
qkvg_kernel(const float* __restrict__ x,
            const float* __restrict__ W,
            const float* __restrict__ cosp,
            const float* __restrict__ sinp,
            const float* __restrict__ tao) {
    extern __shared__ float sm3[];
    float* xs = sm3;              // 64*132 tf32 bits
    float* ws = sm3 + 64 * 132;   // 128*132 tf32 bits (layout [n][k]); reused as os
    int b  = blockIdx.y;
    int n0 = blockIdx.x * 128;
    int tid = threadIdx.x;        // 512

    // fill xs (gathered tokens, tf32-converted)
    for (int i = tid; i < 2048; i += 512) {
        int m  = i >> 5;
        int c4 = i & 31;
        int tok = g_topk[b * 4 + (m >> 4)] * T0_ + (m & 15);
        float4 v = reinterpret_cast<const float4*>(x + ((size_t)b * T_ + tok) * C_)[c4];
        v.x = tf32f(v.x); v.y = tf32f(v.y); v.z = tf32f(v.z); v.w = tf32f(v.w);
        *reinterpret_cast<float4*>(xs + m * 132 + c4 * 4) = v;
    }
    // fill ws[n][k] (direct row copy, tf32-converted)
    for (int i = tid; i < 4096; i += 512) {
        int n  = i >> 5;
        int k4 = i & 31;
        float4 v = reinterpret_cast<const float4*>(W + (size_t)(n0 + n) * C_)[k4];
        v.x = tf32f(v.x); v.y = tf32f(v.y); v.z = tf32f(v.z); v.w = tf32f(v.w);
        *reinterpret_cast<float4*>(ws + n * 132 + k4 * 4) = v;
    }
    __syncthreads();

    int warp = tid >> 5;          // 0..15
    int lane = tid & 31;
    int g = lane >> 2;            // 0..7
    int t = lane & 3;             // 0..3
    int wn = warp * 8;            // n-subtile base

    const unsigned* xsu = reinterpret_cast<const unsigned*>(xs);
    const unsigned* wsu = reinterpret_cast<const unsigned*>(ws);

    float c[4][4];
#pragma unroll
    for (int mt = 0; mt < 4; mt++)
#pragma unroll
        for (int q = 0; q < 4; q++) c[mt][q] = 0.f;

#pragma unroll 4
    for (int ks = 0; ks < 16; ks++) {
        int k0 = ks * 8;
        unsigned b0 = wsu[(wn + g) * 132 + k0 + t];
        unsigned b1 = wsu[(wn + g) * 132 + k0 + t + 4];
#pragma unroll
        for (int mt = 0; mt < 4; mt++) {
            unsigned a0 = xsu[(mt * 16 + g) * 132 + k0 + t];
            unsigned a1 = xsu[(mt * 16 + g + 8) * 132 + k0 + t];
            unsigned a2 = xsu[(mt * 16 + g) * 132 + k0 + t + 4];
            unsigned a3 = xsu[(mt * 16 + g + 8) * 132 + k0 + t + 4];
            mma_tf32(c[mt][0], c[mt][1], c[mt][2], c[mt][3], a0, a1, a2, a3, b0, b1);
        }
    }
    __syncthreads();              // all smem reads done; reuse ws as output

    float* os = ws;               // 64 x 132 result tile
#pragma unroll
    for (int mt = 0; mt < 4; mt++) {
        *reinterpret_cast<float2*>(os + (mt * 16 + g) * 132 + wn + 2 * t) =
            make_float2(c[mt][0], c[mt][1]);
        *reinterpret_cast<float2*>(os + (mt * 16 + g + 8) * 132 + wn + 2 * t) =
            make_float2(c[mt][2], c[mt][3]);
    }
    __syncthreads();

    // ---- fused epilogue (warp = 4 rows of one comp, lane = 4 channels) ----
    int c2 = n0 >> 10;            // 0..3 : token sub-index within groups of 4
    int h  = (n0 >> 7) & 7;       // head
    int ty = warp;
    int tx = lane;
    int comp = ty & 3;            // 0=q 1=k 2=v 3=g (warp-uniform)
    int j = ty >> 2;              // patch 0..3
    int bh = b * 8 + h;
    float t0v = tao[0], t1v = tao[1];

#pragma unroll
    for (int mm = 0; mm < 4; mm++) {
        int m = ty * 4 + mm;
        float4 val = *reinterpret_cast<const float4*>(os + m * 132 + tx * 4);
        int sp = j * 16 + 4 * mm + c2;   // seq position (0..63)
        int s  = sp + 1;                 // incl. sink offset
        if (comp == 2) {
            *reinterpret_cast<float4*>(g_vn + ((size_t)bh * 65 + s) * 128 + tx * 4) = val;
        } else if (comp == 3) {
            float4 o;
            o.x = 1.f / (1.f + __expf(-val.x));
            o.y = 1.f / (1.f + __expf(-val.y));
            o.z = 1.f / (1.f + __expf(-val.z));
            o.w = 1.f / (1.f + __expf(-val.w));
            *reinterpret_cast<float4*>(g_gn + ((size_t)bh * 64 + sp) * 128 + tx * 4) = o;
        } else {
            // rope: partner lane (tx^16) holds the paired half
            float4 p;
            p.x = __shfl_xor_sync(0xffffffffu, val.x, 16);
            p.y = __shfl_xor_sync(0xffffffffu, val.y, 16);
            p.z = __shfl_xor_sync(0xffffffffu, val.z, 16);
            p.w = __shfl_xor_sync(0xffffffffu, val.w, 16);
            float4 cs = *reinterpret_cast<const float4*>(cosp + s * 64 + (tx & 15) * 4);
            float4 sn = *reinterpret_cast<const float4*>(sinp + s * 64 + (tx & 15) * 4);
            float sgn = (tx < 16) ? 1.f : -1.f;
            float4 o;
            o.x = val.x * cs.x + sgn * p.x * sn.x;
            o.y = val.y * cs.y + sgn * p.y * sn.y;
            o.z = val.z * cs.z + sgn * p.z * sn.z;
            o.w = val.w * cs.w + sgn * p.w * sn.w;
            float ss = o.x * o.x + o.y * o.y + o.z * o.z + o.w * o.w;
            for (int off = 16; off; off >>= 1) ss += __shfl_xor_sync(0xffffffffu, ss, off);
            float rn = rsqrtf(ss * (1.0f / 128.0f) + EPS_) * (comp == 0 ? t0v : t1v);
            o.x *= rn; o.y *= rn; o.z *= rn; o.w *= rn;
            float* dst = (comp == 0 ? g_qn : g_kn) + ((size_t)bh * 65 + s) * 128 + tx * 4;
            *reinterpret_cast<float4*>(dst) = o;
        }
    }
}

// ---------------------------------------------------------------------------
// Kernel 4: attention. 256 blocks x 256 threads (4 per (b,h), mod-4 split).
// ---------------------------------------------------------------------------
__global__ void attn_kernel() {
    extern __shared__ float sm4[];
    float* qs  = sm4;                        // 17*132 (own query rows)
    float* ks_ = sm4 + 17 * 132;             // 65*132
    float* vs  = ks_ + 65 * 132;             // 65*132
    float* att = vs + 65 * 132;              // 17*68

    int blk     = blockIdx.x;
    int quarter = blk & 3;
    int bh      = blk >> 2;
    int b = bh >> 3;
    int h = bh & 7;
    int nrows = (65 - quarter + 3) >> 2;     // 17 (q=0) or 16
    int tid  = threadIdx.x;                  // 256
    int warp = tid >> 5;                     // 0..7
    int lane = tid & 31;

    // zero att (upper triangle must be 0 for guard-free AV)
    for (int i = tid; i < 17 * 68; i += 256) att[i] = 0.f;

    const float4* kn = reinterpret_cast<const float4*>(g_kn + (size_t)bh * 65 * 128);
    const float4* vn = reinterpret_cast<const float4*>(g_vn + (size_t)bh * 65 * 128);
    const float4* qn = reinterpret_cast<const float4*>(g_qn + (size_t)bh * 65 * 128);
    for (int s = warp; s < 65; s += 8) {
        *reinterpret_cast<float4*>(ks_ + s * 132 + lane * 4) = kn[s * 32 + lane];
        *reinterpret_cast<float4*>(vs  + s * 132 + lane * 4) = vn[s * 32 + lane];
    }
    for (int i = warp; i < nrows; i += 8) {
        int s = 4 * i + quarter;
        *reinterpret_cast<float4*>(qs + i * 132 + lane * 4) = qn[s * 32 + lane];
    }
    __syncthreads();

    // ---- Score phase: task = (group of 4 own rows, 32-key chunk) -----------
    const float scale = 0.08838834764831845f;  // 1/sqrt(128)
    int ngroups = (nrows + 3) >> 2;
    for (int task = warp; task < ngroups * 3; task += 8) {
        int g = task / 3;
        int c = task - g * 3;
        int i0 = g * 4;
        int imax = min(i0 + 3, nrows - 1);
        int smax = 4 * imax + quarter;
        int t0 = c * 32;
        if (t0 > smax) continue;
        int t  = t0 + lane;
        int te = (t < 64) ? t : 64;
        int ie0 = min(i0 + 0, nrows - 1);
        int ie1 = min(i0 + 1, nrows - 1);
        int ie2 = min(i0 + 2, nrows - 1);
        int ie3 = min(i0 + 3, nrows - 1);

        const float4* kr = reinterpret_cast<const float4*>(ks_ + te * 132);
        const float4* q0 = reinterpret_cast<const float4*>(qs + ie0 * 132);
        const float4* q1 = reinterpret_cast<const float4*>(qs + ie1 * 132);
        const float4* q2 = reinterpret_cast<const float4*>(qs + ie2 * 132);
        const float4* q3 = reinterpret_cast<const float4*>(qs + ie3 * 132);

        float2 p00 = {0,0}, p01 = {0,0}, p10 = {0,0}, p11 = {0,0};
        float2 p20 = {0,0}, p21 = {0,0}, p30 = {0,0}, p31 = {0,0};
#pragma unroll 8
        for (int c4 = 0; c4 < 32; c4++) {
            float4 kv = kr[c4];
            float2 k0 = make_float2(kv.x, kv.y);
            float2 k1 = make_float2(kv.z, kv.w);
            float4 v0 = q0[c4];
            ffma2(p00, make_float2(v0.x, v0.y), k0);
            ffma2(p01, make_float2(v0.z, v0.w), k1);
            float4 v1 = q1[c4];
            ffma2(p10, make_float2(v1.x, v1.y), k0);
            ffma2(p11, make_float2(v1.z, v1.w), k1);
            float4 v2 = q2[c4];
            ffma2(p20, make_float2(v2.x, v2.y), k0);
            ffma2(p21, make_float2(v2.z, v2.w), k1);
            float4 v3 = q3[c4];
            ffma2(p30, make_float2(v3.x, v3.y), k0);
            ffma2(p31, make_float2(v3.z, v3.w), k1);
        }
        float r0 = (p00.x + p00.y) + (p01.x + p01.y);
        float r1 = (p10.x + p10.y) + (p11.x + p11.y);
        float r2 = (p20.x + p20.y) + (p21.x + p21.y);
        float r3 = (p30.x + p30.y) + (p31.x + p31.y);
        int s0v = 4 * (i0 + 0) + quarter;
        int s1v = 4 * (i0 + 1) + quarter;
        int s2v = 4 * (i0 + 2) + quarter;
        int s3v = 4 * (i0 + 3) + quarter;
        if (i0 + 0 < nrows && t <= s0v) att[(i0 + 0) * 68 + t] = r0 * scale;
        if (i0 + 1 < nrows && t <= s1v) att[(i0 + 1) * 68 + t] = r1 * scale;
        if (i0 + 2 < nrows && t <= s2v) att[(i0 + 2) * 68 + t] = r2 * scale;
        if (i0 + 3 < nrows && t <= s3v) att[(i0 + 3) * 68 + t] = r3 * scale;
    }
    __syncthreads();

    // ---- Softmax: one warp per own row ------------------------------------
    for (int i = warp; i < nrows; i += 8) {
        int s = 4 * i + quarter;
        float v0 = (lane      <= s) ? att[i * 68 + lane]      : -3.4e38f;
        float v1 = (lane + 32 <= s) ? att[i * 68 + lane + 32] : -3.4e38f;
        float v2 = (lane + 64 <= s) ? att[i * 68 + lane + 64] : -3.4e38f;
        float m = fmaxf(fmaxf(v0, v1), v2);
        for (int off = 16; off; off >>= 1) m = fmaxf(m, __shfl_xor_sync(0xffffffffu, m, off));
        float e0 = (lane      <= s) ? __expf(v0 - m) : 0.f;
        float e1 = (lane + 32 <= s) ? __expf(v1 - m) : 0.f;
        float e2 = (lane + 64 <= s) ? __expf(v2 - m) : 0.f;
        float sum = e0 + e1 + e2;
        for (int off = 16; off; off >>= 1) sum += __shfl_xor_sync(0xffffffffu, sum, off);
        float inv = 1.f / sum;
        if (lane      <= s) att[i * 68 + lane]      = e0 * inv;
        if (lane + 32 <= s) att[i * 68 + lane + 32] = e1 * inv;
        if (lane + 64 <= s) att[i * 68 + lane + 64] = e2 * inv;
    }
    __syncthreads();

    // ---- AV phase: warp owns rows i = warp + 8*jj -------------------------
    {
        int nj = (warp < nrows) ? ((nrows - warp + 7) >> 3) : 0;   // 0..3
        float2 accp[3][2];
#pragma unroll
        for (int jj = 0; jj < 3; jj++) {
            accp[jj][0] = make_float2(0.f, 0.f);
            accp[jj][1] = make_float2(0.f, 0.f);
        }
        if (nj > 0) {
            int ilast = warp + 8 * (nj - 1);
            int tmax = 4 * ilast + quarter;
            for (int t = 0; t <= tmax; t++) {
                float4 vv = *reinterpret_cast<const float4*>(vs + t * 132 + lane * 4);
                float2 vp0 = make_float2(vv.x, vv.y);
                float2 vp1 = make_float2(vv.z, vv.w);
#pragma unroll
                for (int jj = 0; jj < 3; jj++) {
                    if (jj < nj) {
                        float a = att[(warp + 8 * jj) * 68 + t];   // 0 for t > s
                        float2 ap = make_float2(a, a);
                        ffma2(accp[jj][0], ap, vp0);
                        ffma2(accp[jj][1], ap, vp1);
                    }
                }
            }
#pragma unroll
            for (int jj = 0; jj < 3; jj++) {
                if (jj < nj) {
                    int i = warp + 8 * jj;
                    int s = 4 * i + quarter;
                    if (s == 0) continue;
                    int sp = s - 1;
                    float4 gv = *reinterpret_cast<const float4*>(
                        g_gn + ((size_t)bh * 64 + sp) * 128 + lane * 4);
                    float4 o;
                    o.x = accp[jj][0].x * gv.x;
                    o.y = accp[jj][0].y * gv.y;
                    o.z = accp[jj][1].x * gv.z;
                    o.w = accp[jj][1].y * gv.w;
                    *reinterpret_cast<float4*>(
                        g_y + (size_t)(b * 64 + sp) * 1024 + h * C_ + lane * 4) = o;
                }
            }
        }
    }
}

// ---------------------------------------------------------------------------
// Kernel 5: output GEMM via tf32 mma.sync, split-K (8 chunks) + N split (2).
// Grid (8 kc, 2 nt, 8 b) = 128 blocks x 256 threads. M=64, N=64, K=128.
// ---------------------------------------------------------------------------
__global__ void __launch_bounds__(256, 2)
outgemm_kernel(const float* __restrict__ Wout) {
    extern __shared__ float smO[];
    float* ys = smO;              // 64*132 tf32 bits
    float* wo = smO + 64 * 132;   // 64*132 tf32 bits, [n][k]
    int kc = blockIdx.x;          // 0..7
    int nt = blockIdx.y;          // 0..1
    int b  = blockIdx.z;          // 0..7
    int k0 = kc * 128;
    int tid = threadIdx.x;        // 256

    for (int i = tid; i < 2048; i += 256) {
        int m  = i >> 5;
        int k4 = i & 31;
        float4 v = *reinterpret_cast<const float4*>(
            g_y + (size_t)(b * 64 + m) * 1024 + k0 + k4 * 4);
        v.x = tf32f(v.x); v.y = tf32f(v.y); v.z = tf32f(v.z); v.w = tf32f(v.w);
        *reinterpret_cast<float4*>(ys + m * 132 + k4 * 4) = v;
    }
    for (int i = tid; i < 2048; i += 256) {
        int n  = i >> 5;
        int k4 = i & 31;
        float4 v = *reinterpret_cast<const float4*>(
            Wout + (size_t)(nt * 64 + n) * 1024 + k0 + k4 * 4);
        v.x = tf32f(v.x); v.y = tf32f(v.y); v.z = tf32f(v.z); v.w = tf32f(v.w);
        *reinterpret_cast<float4*>(wo + n * 132 + k4 * 4) = v;
    }
    __syncthreads();

    int warp = tid >> 5;          // 0..7
    int lane = tid & 31;
    int g = lane >> 2;            // 0..7
    int t = lane & 3;             // 0..3
    int wn = warp * 8;            // n within 64-tile

    const unsigned* ysu = reinterpret_cast<const unsigned*>(ys);
    const unsigned* wou = reinterpret_cast<const unsigned*>(wo);

    float c[4][4];
#pragma unroll
    for (int mt = 0; mt < 4; mt++)
#pragma unroll
        for (int q = 0; q < 4; q++) c[mt][q] = 0.f;

#pragma unroll 4
    for (int ks = 0; ks < 16; ks++) {
        int kk = ks * 8;
        unsigned b0 = wou[(wn + g) * 132 + kk + t];
        unsigned b1 = wou[(wn + g) * 132 + kk + t + 4];
#pragma unroll
        for (int mt = 0; mt < 4; mt++) {
            unsigned a0 = ysu[(mt * 16 + g) * 132 + kk + t];
            unsigned a1 = ysu[(mt * 16 + g + 8) * 132 + kk + t];
            unsigned a2 = ysu[(mt * 16 + g) * 132 + kk + t + 4];
            unsigned a3 = ysu[(mt * 16 + g + 8) * 132 + kk + t + 4];
            mma_tf32(c[mt][0], c[mt][1], c[mt][2], c[mt][3], a0, a1, a2, a3, b0, b1);
        }
    }

    // write fragments directly to split-K partials
    float* part = g_part + (size_t)kc * 65536;
    int col = nt * 64 + wn + 2 * t;
#pragma unroll
    for (int mt = 0; mt < 4; mt++) {
        int row0 = mt * 16 + g;
        int row1 = mt * 16 + g + 8;
        *reinterpret_cast<float2*>(part + (size_t)(b * 64 + row0) * 128 + col) =
            make_float2(c[mt][0], c[mt][1]);
        *reinterpret_cast<float2*>(part + (size_t)(b * 64 + row1) * 128 + col) =
            make_float2(c[mt][2], c[mt][3]);
    }
}

__global__ void reduce_kernel(float* __restrict__ out) {
    int i = blockIdx.x * 256 + threadIdx.x;
    float s = 0.f;
#pragma unroll
    for (int kc = 0; kc < 8; kc++) s += g_part[kc * 65536 + i];
    out[i] = s;
}

// ---------------------------------------------------------------------------
extern "C" void kernel_launch(void* const* d_in, const int* in_sizes, int n_in,
                              void* d_out, int out_size) {
    const float* x      = (const float*)d_in[0];
    const float* cosp   = (const float*)d_in[1];
    const float* sinp   = (const float*)d_in[2];
    const float* sink   = (const float*)d_in[3];
    const float* W_qkvg = (const float*)d_in[4];
    const float* patchw = (const float*)d_in[5];
    const float* W_out  = (const float*)d_in[6];
    const float* tao    = (const float*)d_in[7];
    float* out = (float*)d_out;

    const int smem3 = (64 * 132 + 128 * 132) * 4;                        // ~101 KB
    const int smem4 = (17 * 132 + 2 * 65 * 132 + 17 * 68) * 4;           // ~82 KB
    const int smemO = (2 * 64 * 132) * 4;                                // ~68 KB
    cudaFuncSetAttribute(qkvg_kernel, cudaFuncAttributeMaxDynamicSharedMemorySize, smem3);
    cudaFuncSetAttribute(attn_kernel, cudaFuncAttributeMaxDynamicSharedMemorySize, smem4);
    cudaFuncSetAttribute(outgemm_kernel, cudaFuncAttributeMaxDynamicSharedMemorySize, smemO);

    patch_score_kernel<<<B_ * NP_, 256>>>(x, patchw);
    topk_kernel<<<B_, 32>>>();
    sink_prep_kernel<<<1, 256>>>(sink, tao);
    qkvg_kernel<<<dim3(32, B_), 512, smem3>>>(x, W_qkvg, cosp, sinp, tao);
    attn_kernel<<<B_ * H_ * 4, 256, smem4>>>();
    outgemm_kernel<<<dim3(8, 2, B_), 256, smemO>>>(W_out);
    reduce_kernel<<<B_ * 64 * 128 / 256, 256>>>(out);
}

// round 17
// speedup vs baseline: 1.9960x; 1.0484x over previous
#include <cuda_runtime.h>
#include <cuda_bf16.h>
#include <math.h>

// Problem constants
#define B_   8
#define T_   8192
#define C_   128
#define H_   8
#define T0_  16
#define NP_  512           // T/T0
#define S_   65            // 4 patches * 16 + 1 sink
#define EPS_ 1.1920929e-07f

// Scratch (device globals; no allocation allowed)
__device__ float g_logits[B_ * NP_];             // 4096
__device__ int   g_topk[B_ * 4];                 // sorted patch indices per batch
__device__ float g_qn[B_ * H_ * 65 * 128];       // prenormed q (rope+rmsnorm+tao0), row 0 = sink
__device__ float g_kn[B_ * H_ * 65 * 128];       // prenormed k
__device__ float g_vn[B_ * H_ * 65 * 128];       // raw v
__device__ float g_gn[B_ * H_ * 64 * 128];       // sigmoid(g)
__device__ float g_y[B_ * 64 * 1024];            // gated attention output
__device__ float g_part[8 * B_ * 64 * 128];      // split-K partials of final GEMM

// Packed fp32 pair FMA: d = a*b + d (both lanes)
__device__ __forceinline__ void ffma2(float2& d, float2 a, float2 b) {
    asm("fma.rn.f32x2 %0, %1, %2, %0;"
        : "+l"(reinterpret_cast<unsigned long long&>(d))
        : "l"(reinterpret_cast<unsigned long long&>(a)),
          "l"(reinterpret_cast<unsigned long long&>(b)));
}

__device__ __forceinline__ float tf32f(float f) {
    float r;
    asm("cvt.rna.tf32.f32 %0, %1;" : "=f"(r) : "f"(f));
    return r;
}

__device__ __forceinline__ void mma_tf32(float& c0, float& c1, float& c2, float& c3,
                                         unsigned a0, unsigned a1, unsigned a2, unsigned a3,
                                         unsigned b0, unsigned b1) {
    asm volatile("mma.sync.aligned.m16n8k8.row.col.f32.tf32.tf32.f32 "
        "{%0,%1,%2,%3}, {%4,%5,%6,%7}, {%8,%9}, {%0,%1,%2,%3};"
        : "+f"(c0), "+f"(c1), "+f"(c2), "+f"(c3)
        : "r"(a0), "r"(a1), "r"(a2), "r"(a3), "r"(b0), "r"(b1));
}

__device__ __forceinline__ void ldsm_x4(unsigned& r0, unsigned& r1, unsigned& r2, unsigned& r3,
                                        unsigned addr) {
    asm volatile("ldmatrix.sync.aligned.m8n8.x4.shared.b16 {%0,%1,%2,%3}, [%4];"
        : "=r"(r0), "=r"(r1), "=r"(r2), "=r"(r3) : "r"(addr));
}

__device__ __forceinline__ void ldsm_x2(unsigned& r0, unsigned& r1, unsigned addr) {
    asm volatile("ldmatrix.sync.aligned.m8n8.x2.shared.b16 {%0,%1}, [%2];"
        : "=r"(r0), "=r"(r1) : "r"(addr));
}

// ---------------------------------------------------------------------------
// Kernel 1: patch score logits.
// ---------------------------------------------------------------------------
__global__ void patch_score_kernel(const float* __restrict__ x,
                                   const float* __restrict__ pw) {
    int blk = blockIdx.x;                  // b*512 + p
    const float4* v = reinterpret_cast<const float4*>(x + (size_t)blk * 2048);
    const float4* w = reinterpret_cast<const float4*>(pw);
    float ssq = 0.f, dot = 0.f;
    for (int i = threadIdx.x; i < 512; i += 256) {
        float4 a = v[i];
        float4 b = w[i];
        ssq += a.x * a.x + a.y * a.y + a.z * a.z + a.w * a.w;
        dot += a.x * b.x + a.y * b.y + a.z * b.z + a.w * b.w;
    }
    for (int off = 16; off; off >>= 1) {
        ssq += __shfl_xor_sync(0xffffffffu, ssq, off);
        dot += __shfl_xor_sync(0xffffffffu, dot, off);
    }
    __shared__ float red[16];
    int wid = threadIdx.x >> 5, lane = threadIdx.x & 31;
    if (lane == 0) { red[wid] = ssq; red[8 + wid] = dot; }
    __syncthreads();
    if (threadIdx.x == 0) {
        float S = 0.f, D = 0.f;
        for (int wv = 0; wv < 8; wv++) { S += red[wv]; D += red[8 + wv]; }
        g_logits[blk] = D * rsqrtf(S * (1.0f / 2048.0f) + EPS_);
    }
}

// ---------------------------------------------------------------------------
// Kernel 2 (merged): blocks 0-7 = top-4 per batch (warp 0 only);
// block 8 = sink row prep (rope at s=0 is identity).
// ---------------------------------------------------------------------------
__global__ void prep_kernel(const float* __restrict__ sink,
                            const float* __restrict__ tao) {
    if (blockIdx.x < 8) {
        if (threadIdx.x >= 32) return;
        int b = blockIdx.x;
        int lane = threadIdx.x;
        float vals[16];
        for (int i = 0; i < 16; i++) vals[i] = g_logits[b * NP_ + lane * 16 + i];
        int chosen[4];
        for (int r = 0; r < 4; r++) {
            float best = -3.4e38f;
            int bi = 0x7fffffff;
            for (int i = 0; i < 16; i++) {
                int idx = lane * 16 + i;
                bool used = false;
                for (int j = 0; j < r; j++) if (chosen[j] == idx) used = true;
                if (!used && vals[i] > best) { best = vals[i]; bi = idx; }
            }
            for (int off = 16; off; off >>= 1) {
                float ov = __shfl_down_sync(0xffffffffu, best, off);
                int   oi = __shfl_down_sync(0xffffffffu, bi, off);
                if (ov > best || (ov == best && oi < bi)) { best = ov; bi = oi; }
            }
            bi = __shfl_sync(0xffffffffu, bi, 0);
            chosen[r] = bi;
        }
        if (lane == 0) {
            for (int i = 0; i < 3; i++)
                for (int j = i + 1; j < 4; j++)
                    if (chosen[j] < chosen[i]) { int t = chosen[i]; chosen[i] = chosen[j]; chosen[j] = t; }
            for (int i = 0; i < 4; i++) g_topk[b * 4 + i] = chosen[i];
        }
    } else {
        int warp = threadIdx.x >> 5;   // h (0..7)
        int lane = threadIdx.x & 31;
        float t0v = tao[0], t1v = tao[1];
        float4 a = *reinterpret_cast<const float4*>(sink + warp * 128 + lane * 4);
        float ss = a.x * a.x + a.y * a.y + a.z * a.z + a.w * a.w;
        for (int off = 16; off; off >>= 1) ss += __shfl_xor_sync(0xffffffffu, ss, off);
        float rq = rsqrtf(ss * (1.0f / 128.0f) + EPS_) * t0v;
        float rk = rsqrtf(ss * (1.0f / 128.0f) + EPS_) * t1v;
        float4 q = make_float4(a.x * rq, a.y * rq, a.z * rq, a.w * rq);
        float4 k = make_float4(a.x * rk, a.y * rk, a.z * rk, a.w * rk);
        for (int b = 0; b < 8; b++) {
            size_t base = ((size_t)(b * 8 + warp) * 65) * 128 + lane * 4;
            *reinterpret_cast<float4*>(g_qn + base) = q;
            *reinterpret_cast<float4*>(g_kn + base) = k;
            *reinterpret_cast<float4*>(g_vn + base) = a;
        }
    }
}

// ---------------------------------------------------------------------------
// Kernel 3: qkvg projection via tf32 mma.sync (ldmatrix fragment loads) +
// fused rope/rmsnorm/sigmoid epilogue. 512 threads, 16 warps.
// ---------------------------------------------------------------------------
__global__ void __launch_bounds__(512, 2)
qkvg_kernel(const float* __restrict__ x,
            const float* __restrict__ W,
            const float* __restrict__ cosp,
            const float* __restrict__ sinp,
            const float* __restrict__ tao) {
    extern __shared__ float sm3[];
    float* xs = sm3;              // 64*132 tf32 bits
    float* ws = sm3 + 64 * 132;   // 128*132 tf32 bits (layout [n][k]); reused as os
    int b  = blockIdx.y;
    int n0 = blockIdx.x * 128;
    int tid = threadIdx.x;        // 512

    // fill xs (gathered tokens, tf32-converted)
    for (int i = tid; i < 2048; i += 512) {
        int m  = i >> 5;
        int c4 = i & 31;
        int tok = g_topk[b * 4 + (m >> 4)] * T0_ + (m & 15);
        float4 v = reinterpret_cast<const float4*>(x + ((size_t)b * T_ + tok) * C_)[c4];
        v.x = tf32f(v.x); v.y = tf32f(v.y); v.z = tf32f(v.z); v.w = tf32f(v.w);
        *reinterpret_cast<float4*>(xs + m * 132 + c4 * 4) = v;
    }
    // fill ws[n][k] (direct row copy, tf32-converted)
    for (int i = tid; i < 4096; i += 512) {
        int n  = i >> 5;
        int k4 = i & 31;
        float4 v = reinterpret_cast<const float4*>(W + (size_t)(n0 + n) * C_)[k4];
        v.x = tf32f(v.x); v.y = tf32f(v.y); v.z = tf32f(v.z); v.w = tf32f(v.w);
        *reinterpret_cast<float4*>(ws + n * 132 + k4 * 4) = v;
    }
    __syncthreads();

    int warp = tid >> 5;          // 0..15
    int lane = tid & 31;
    int g = lane >> 2;            // 0..7
    int t = lane & 3;             // 0..3
    int wn = warp * 8;            // n-subtile base

    // ldmatrix per-lane source addresses
    int q4 = lane >> 3, r8 = lane & 7;
    unsigned xs_sa = (unsigned)__cvta_generic_to_shared(xs);
    unsigned ws_sa = (unsigned)__cvta_generic_to_shared(ws);
    unsigned a_base = xs_sa + (unsigned)((((q4 & 1) * 8 + r8) * 132 + (q4 >> 1) * 4) * 4);
    unsigned b_base = ws_sa + (unsigned)(((wn + (lane & 7)) * 132 + ((lane >> 3) & 1) * 4) * 4);

    float c[4][4];
#pragma unroll
    for (int mt = 0; mt < 4; mt++)
#pragma unroll
        for (int q = 0; q < 4; q++) c[mt][q] = 0.f;

#pragma unroll 4
    for (int ks = 0; ks < 16; ks++) {
        unsigned b0, b1;
        ldsm_x2(b0, b1, b_base + ks * 32);
#pragma unroll
        for (int mt = 0; mt < 4; mt++) {
            unsigned a0, a1, a2, a3;
            ldsm_x4(a0, a1, a2, a3, a_base + (unsigned)(mt * 16 * 132 * 4) + ks * 32);
            mma_tf32(c[mt][0], c[mt][1], c[mt][2], c[mt][3], a0, a1, a2, a3, b0, b1);
        }
    }
    __syncthreads();              // all smem reads done; reuse ws as output

    float* os = ws;               // 64 x 132 result tile
#pragma unroll
    for (int mt = 0; mt < 4; mt++) {
        *reinterpret_cast<float2*>(os + (mt * 16 + g) * 132 + wn + 2 * t) =
            make_float2(c[mt][0], c[mt][1]);
        *reinterpret_cast<float2*>(os + (mt * 16 + g + 8) * 132 + wn + 2 * t) =
            make_float2(c[mt][2], c[mt][3]);
    }
    __syncthreads();

    // ---- fused epilogue (warp = 4 rows of one comp, lane = 4 channels) ----
    int c2 = n0 >> 10;            // 0..3 : token sub-index within groups of 4
    int h  = (n0 >> 7) & 7;       // head
    int ty = warp;
    int tx = lane;
    int comp = ty & 3;            // 0=q 1=k 2=v 3=g (warp-uniform)
    int j = ty >> 2;              // patch 0..3
    int bh = b * 8 + h;
    float t0v = tao[0], t1v = tao[1];

#pragma unroll
    for (int mm = 0; mm < 4; mm++) {
        int m = ty * 4 + mm;
        float4 val = *reinterpret_cast<const float4*>(os + m * 132 + tx * 4);
        int sp = j * 16 + 4 * mm + c2;   // seq position (0..63)
        int s  = sp + 1;                 // incl. sink offset
        if (comp == 2) {
            *reinterpret_cast<float4*>(g_vn + ((size_t)bh * 65 + s) * 128 + tx * 4) = val;
        } else if (comp == 3) {
            float4 o;
            o.x = 1.f / (1.f + __expf(-val.x));
            o.y = 1.f / (1.f + __expf(-val.y));
            o.z = 1.f / (1.f + __expf(-val.z));
            o.w = 1.f / (1.f + __expf(-val.w));
            *reinterpret_cast<float4*>(g_gn + ((size_t)bh * 64 + sp) * 128 + tx * 4) = o;
        } else {
            // rope: partner lane (tx^16) holds the paired half
            float4 p;
            p.x = __shfl_xor_sync(0xffffffffu, val.x, 16);
            p.y = __shfl_xor_sync(0xffffffffu, val.y, 16);
            p.z = __shfl_xor_sync(0xffffffffu, val.z, 16);
            p.w = __shfl_xor_sync(0xffffffffu, val.w, 16);
            float4 cs = *reinterpret_cast<const float4*>(cosp + s * 64 + (tx & 15) * 4);
            float4 sn = *reinterpret_cast<const float4*>(sinp + s * 64 + (tx & 15) * 4);
            float sgn = (tx < 16) ? 1.f : -1.f;
            float4 o;
            o.x = val.x * cs.x + sgn * p.x * sn.x;
            o.y = val.y * cs.y + sgn * p.y * sn.y;
            o.z = val.z * cs.z + sgn * p.z * sn.z;
            o.w = val.w * cs.w + sgn * p.w * sn.w;
            float ss = o.x * o.x + o.y * o.y + o.z * o.z + o.w * o.w;
            for (int off = 16; off; off >>= 1) ss += __shfl_xor_sync(0xffffffffu, ss, off);
            float rn = rsqrtf(ss * (1.0f / 128.0f) + EPS_) * (comp == 0 ? t0v : t1v);
            o.x *= rn; o.y *= rn; o.z *= rn; o.w *= rn;
            float* dst = (comp == 0 ? g_qn : g_kn) + ((size_t)bh * 65 + s) * 128 + tx * 4;
            *reinterpret_cast<float4*>(dst) = o;
        }
    }
}

// ---------------------------------------------------------------------------
// Kernel 4: attention. 256 blocks x 256 threads (4 per (b,h), mod-4 split).
// ---------------------------------------------------------------------------
__global__ void attn_kernel() {
    extern __shared__ float sm4[];
    float* qs  = sm4;                        // 17*132 (own query rows)
    float* ks_ = sm4 + 17 * 132;             // 65*132
    float* vs  = ks_ + 65 * 132;             // 65*132
    float* att = vs + 65 * 132;              // 17*68

    int blk     = blockIdx.x;
    int quarter = blk & 3;
    int bh      = blk >> 2;
    int b = bh >> 3;
    int h = bh & 7;
    int nrows = (65 - quarter + 3) >> 2;     // 17 (q=0) or 16
    int tid  = threadIdx.x;                  // 256
    int warp = tid >> 5;                     // 0..7
    int lane = tid & 31;

    // zero att (upper triangle must be 0 for guard-free AV)
    for (int i = tid; i < 17 * 68; i += 256) att[i] = 0.f;

    const float4* kn = reinterpret_cast<const float4*>(g_kn + (size_t)bh * 65 * 128);
    const float4* vn = reinterpret_cast<const float4*>(g_vn + (size_t)bh * 65 * 128);
    const float4* qn = reinterpret_cast<const float4*>(g_qn + (size_t)bh * 65 * 128);
    for (int s = warp; s < 65; s += 8) {
        *reinterpret_cast<float4*>(ks_ + s * 132 + lane * 4) = kn[s * 32 + lane];
        *reinterpret_cast<float4*>(vs  + s * 132 + lane * 4) = vn[s * 32 + lane];
    }
    for (int i = warp; i < nrows; i += 8) {
        int s = 4 * i + quarter;
        *reinterpret_cast<float4*>(qs + i * 132 + lane * 4) = qn[s * 32 + lane];
    }
    __syncthreads();

    // ---- Score phase: task = (group of 4 own rows, 32-key chunk) -----------
    const float scale = 0.08838834764831845f;  // 1/sqrt(128)
    int ngroups = (nrows + 3) >> 2;
    for (int task = warp; task < ngroups * 3; task += 8) {
        int g = task / 3;
        int c = task - g * 3;
        int i0 = g * 4;
        int imax = min(i0 + 3, nrows - 1);
        int smax = 4 * imax + quarter;
        int t0 = c * 32;
        if (t0 > smax) continue;
        int t  = t0 + lane;
        int te = (t < 64) ? t : 64;
        int ie0 = min(i0 + 0, nrows - 1);
        int ie1 = min(i0 + 1, nrows - 1);
        int ie2 = min(i0 + 2, nrows - 1);
        int ie3 = min(i0 + 3, nrows - 1);

        const float4* kr = reinterpret_cast<const float4*>(ks_ + te * 132);
        const float4* q0 = reinterpret_cast<const float4*>(qs + ie0 * 132);
        const float4* q1 = reinterpret_cast<const float4*>(qs + ie1 * 132);
        const float4* q2 = reinterpret_cast<const float4*>(qs + ie2 * 132);
        const float4* q3 = reinterpret_cast<const float4*>(qs + ie3 * 132);

        float2 p00 = {0,0}, p01 = {0,0}, p10 = {0,0}, p11 = {0,0};
        float2 p20 = {0,0}, p21 = {0,0}, p30 = {0,0}, p31 = {0,0};
#pragma unroll 8
        for (int c4 = 0; c4 < 32; c4++) {
            float4 kv = kr[c4];
            float2 k0 = make_float2(kv.x, kv.y);
            float2 k1 = make_float2(kv.z, kv.w);
            float4 v0 = q0[c4];
            ffma2(p00, make_float2(v0.x, v0.y), k0);
            ffma2(p01, make_float2(v0.z, v0.w), k1);
            float4 v1 = q1[c4];
            ffma2(p10, make_float2(v1.x, v1.y), k0);
            ffma2(p11, make_float2(v1.z, v1.w), k1);
            float4 v2 = q2[c4];
            ffma2(p20, make_float2(v2.x, v2.y), k0);
            ffma2(p21, make_float2(v2.z, v2.w), k1);
            float4 v3 = q3[c4];
            ffma2(p30, make_float2(v3.x, v3.y), k0);
            ffma2(p31, make_float2(v3.z, v3.w), k1);
        }
        float r0 = (p00.x + p00.y) + (p01.x + p01.y);
        float r1 = (p10.x + p10.y) + (p11.x + p11.y);
        float r2 = (p20.x + p20.y) + (p21.x + p21.y);
        float r3 = (p30.x + p30.y) + (p31.x + p31.y);
        int s0v = 4 * (i0 + 0) + quarter;
        int s1v = 4 * (i0 + 1) + quarter;
        int s2v = 4 * (i0 + 2) + quarter;
        int s3v = 4 * (i0 + 3) + quarter;
        if (i0 + 0 < nrows && t <= s0v) att[(i0 + 0) * 68 + t] = r0 * scale;
        if (i0 + 1 < nrows && t <= s1v) att[(i0 + 1) * 68 + t] = r1 * scale;
        if (i0 + 2 < nrows && t <= s2v) att[(i0 + 2) * 68 + t] = r2 * scale;
        if (i0 + 3 < nrows && t <= s3v) att[(i0 + 3) * 68 + t] = r3 * scale;
    }
    __syncthreads();

    // ---- Softmax: one warp per own row ------------------------------------
    for (int i = warp; i < nrows; i += 8) {
        int s = 4 * i + quarter;
        float v0 = (lane      <= s) ? att[i * 68 + lane]      : -3.4e38f;
        float v1 = (lane + 32 <= s) ? att[i * 68 + lane + 32] : -3.4e38f;
        float v2 = (lane + 64 <= s) ? att[i * 68 + lane + 64] : -3.4e38f;
        float m = fmaxf(fmaxf(v0, v1), v2);
        for (int off = 16; off; off >>= 1) m = fmaxf(m, __shfl_xor_sync(0xffffffffu, m, off));
        float e0 = (lane      <= s) ? __expf(v0 - m) : 0.f;
        float e1 = (lane + 32 <= s) ? __expf(v1 - m) : 0.f;
        float e2 = (lane + 64 <= s) ? __expf(v2 - m) : 0.f;
        float sum = e0 + e1 + e2;
        for (int off = 16; off; off >>= 1) sum += __shfl_xor_sync(0xffffffffu, sum, off);
        float inv = 1.f / sum;
        if (lane      <= s) att[i * 68 + lane]      = e0 * inv;
        if (lane + 32 <= s) att[i * 68 + lane + 32] = e1 * inv;
        if (lane + 64 <= s) att[i * 68 + lane + 64] = e2 * inv;
    }
    __syncthreads();

    // ---- AV phase: warp owns rows i = warp + 8*jj -------------------------
    {
        int nj = (warp < nrows) ? ((nrows - warp + 7) >> 3) : 0;   // 0..3
        float2 accp[3][2];
#pragma unroll
        for (int jj = 0; jj < 3; jj++) {
            accp[jj][0] = make_float2(0.f, 0.f);
            accp[jj][1] = make_float2(0.f, 0.f);
        }
        if (nj > 0) {
            int ilast = warp + 8 * (nj - 1);
            int tmax = 4 * ilast + quarter;
            for (int t = 0; t <= tmax; t++) {
                float4 vv = *reinterpret_cast<const float4*>(vs + t * 132 + lane * 4);
                float2 vp0 = make_float2(vv.x, vv.y);
                float2 vp1 = make_float2(vv.z, vv.w);
#pragma unroll
                for (int jj = 0; jj < 3; jj++) {
                    if (jj < nj) {
                        float a = att[(warp + 8 * jj) * 68 + t];   // 0 for t > s
                        float2 ap = make_float2(a, a);
                        ffma2(accp[jj][0], ap, vp0);
                        ffma2(accp[jj][1], ap, vp1);
                    }
                }
            }
#pragma unroll
            for (int jj = 0; jj < 3; jj++) {
                if (jj < nj) {
                    int i = warp + 8 * jj;
                    int s = 4 * i + quarter;
                    if (s == 0) continue;
                    int sp = s - 1;
                    float4 gv = *reinterpret_cast<const float4*>(
                        g_gn + ((size_t)bh * 64 + sp) * 128 + lane * 4);
                    float4 o;
                    o.x = accp[jj][0].x * gv.x;
                    o.y = accp[jj][0].y * gv.y;
                    o.z = accp[jj][1].x * gv.z;
                    o.w = accp[jj][1].y * gv.w;
                    *reinterpret_cast<float4*>(
                        g_y + (size_t)(b * 64 + sp) * 1024 + h * C_ + lane * 4) = o;
                }
            }
        }
    }
}

// ---------------------------------------------------------------------------
// Kernel 5: output GEMM via tf32 mma.sync (ldmatrix loads), split-K (8) + N(2).
// Grid (8 kc, 2 nt, 8 b) = 128 blocks x 256 threads. M=64, N=64, K=128.
// ---------------------------------------------------------------------------
__global__ void __launch_bounds__(256, 2)
outgemm_kernel(const float* __restrict__ Wout) {
    extern __shared__ float smO[];
    float* ys = smO;              // 64*132 tf32 bits
    float* wo = smO + 64 * 132;   // 64*132 tf32 bits, [n][k]
    int kc = blockIdx.x;          // 0..7
    int nt = blockIdx.y;          // 0..1
    int b  = blockIdx.z;          // 0..7
    int k0 = kc * 128;
    int tid = threadIdx.x;        // 256

    for (int i = tid; i < 2048; i += 256) {
        int m  = i >> 5;
        int k4 = i & 31;
        float4 v = *reinterpret_cast<const float4*>(
            g_y + (size_t)(b * 64 + m) * 1024 + k0 + k4 * 4);
        v.x = tf32f(v.x); v.y = tf32f(v.y); v.z = tf32f(v.z); v.w = tf32f(v.w);
        *reinterpret_cast<float4*>(ys + m * 132 + k4 * 4) = v;
    }
    for (int i = tid; i < 2048; i += 256) {
        int n  = i >> 5;
        int k4 = i & 31;
        float4 v = *reinterpret_cast<const float4*>(
            Wout + (size_t)(nt * 64 + n) * 1024 + k0 + k4 * 4);
        v.x = tf32f(v.x); v.y = tf32f(v.y); v.z = tf32f(v.z); v.w = tf32f(v.w);
        *reinterpret_cast<float4*>(wo + n * 132 + k4 * 4) = v;
    }
    __syncthreads();

    int warp = tid >> 5;          // 0..7
    int lane = tid & 31;
    int g = lane >> 2;            // 0..7
    int t = lane & 3;             // 0..3
    int wn = warp * 8;            // n within 64-tile

    int q4 = lane >> 3, r8 = lane & 7;
    unsigned ys_sa = (unsigned)__cvta_generic_to_shared(ys);
    unsigned wo_sa = (unsigned)__cvta_generic_to_shared(wo);
    unsigned a_base = ys_sa + (unsigned)((((q4 & 1) * 8 + r8) * 132 + (q4 >> 1) * 4) * 4);
    unsigned b_base = wo_sa + (unsigned)(((wn + (lane & 7)) * 132 + ((lane >> 3) & 1) * 4) * 4);

    float c[4][4];
#pragma unroll
    for (int mt = 0; mt < 4; mt++)
#pragma unroll
        for (int q = 0; q < 4; q++) c[mt][q] = 0.f;

#pragma unroll 4
    for (int ks = 0; ks < 16; ks++) {
        unsigned b0, b1;
        ldsm_x2(b0, b1, b_base + ks * 32);
#pragma unroll
        for (int mt = 0; mt < 4; mt++) {
            unsigned a0, a1, a2, a3;
            ldsm_x4(a0, a1, a2, a3, a_base + (unsigned)(mt * 16 * 132 * 4) + ks * 32);
            mma_tf32(c[mt][0], c[mt][1], c[mt][2], c[mt][3], a0, a1, a2, a3, b0, b1);
        }
    }

    // write fragments directly to split-K partials
    float* part = g_part + (size_t)kc * 65536;
    int col = nt * 64 + wn + 2 * t;
#pragma unroll
    for (int mt = 0; mt < 4; mt++) {
        int row0 = mt * 16 + g;
        int row1 = mt * 16 + g + 8;
        *reinterpret_cast<float2*>(part + (size_t)(b * 64 + row0) * 128 + col) =
            make_float2(c[mt][0], c[mt][1]);
        *reinterpret_cast<float2*>(part + (size_t)(b * 64 + row1) * 128 + col) =
            make_float2(c[mt][2], c[mt][3]);
    }
}

__global__ void reduce_kernel(float* __restrict__ out) {
    int i = blockIdx.x * 256 + threadIdx.x;
    float s = 0.f;
#pragma unroll
    for (int kc = 0; kc < 8; kc++) s += g_part[kc * 65536 + i];
    out[i] = s;
}

// ---------------------------------------------------------------------------
extern "C" void kernel_launch(void* const* d_in, const int* in_sizes, int n_in,
                              void* d_out, int out_size) {
    const float* x      = (const float*)d_in[0];
    const float* cosp   = (const float*)d_in[1];
    const float* sinp   = (const float*)d_in[2];
    const float* sink   = (const float*)d_in[3];
    const float* W_qkvg = (const float*)d_in[4];
    const float* patchw = (const float*)d_in[5];
    const float* W_out  = (const float*)d_in[6];
    const float* tao    = (const float*)d_in[7];
    float* out = (float*)d_out;

    const int smem3 = (64 * 132 + 128 * 132) * 4;                        // ~101 KB
    const int smem4 = (17 * 132 + 2 * 65 * 132 + 17 * 68) * 4;           // ~82 KB
    const int smemO = (2 * 64 * 132) * 4;                                // ~68 KB
    cudaFuncSetAttribute(qkvg_kernel, cudaFuncAttributeMaxDynamicSharedMemorySize, smem3);
    cudaFuncSetAttribute(attn_kernel, cudaFuncAttributeMaxDynamicSharedMemorySize, smem4);
    cudaFuncSetAttribute(outgemm_kernel, cudaFuncAttributeMaxDynamicSharedMemorySize, smemO);

    patch_score_kernel<<<B_ * NP_, 256>>>(x, patchw);
    prep_kernel<<<9, 256>>>(sink, tao);
    qkvg_kernel<<<dim3(32, B_), 512, smem3>>>(x, W_qkvg, cosp, sinp, tao);
    attn_kernel<<<B_ * H_ * 4, 256, smem4>>>();
    outgemm_kernel<<<dim3(8, 2, B_), 256, smemO>>>(W_out);
    reduce_kernel<<<B_ * 64 * 128 / 256, 256>>>(out);
}